// round 1
// baseline (speedup 1.0000x reference)
#include <cuda_runtime.h>

#define GN 4096   // N*N
#define TT 168    // T
#define BB 128    // B
#define NN 64     // N
#define PP 128    // P

// Scratch (allocation-free rule: __device__ globals)
__device__ float d_w2[GN];
__device__ float d_v[GN];

// ---------------------------------------------------------------------------
// Kernel 1: w2[k] = weights[k]^2
// ---------------------------------------------------------------------------
__global__ void k_w2(const float* __restrict__ w) {
    int i = blockIdx.x * 256 + threadIdx.x;
    if (i < GN) {
        float t = w[i];
        d_w2[i] = t * t;
    }
}

// ---------------------------------------------------------------------------
// Kernel 2: v = g @ w2  (one block per row), fused F[i,t] = v[i]*alpha[t]
// g row = 16 KB; each of 256 threads does 4 independent float4 loads (MLP=8
// counting the w2 pair, hides DRAM latency), then block reduction.
// ---------------------------------------------------------------------------
__global__ void __launch_bounds__(256) k_matvec(const float* __restrict__ g,
                                                const float* __restrict__ alphas,
                                                float* __restrict__ Fout) {
    const int row = blockIdx.x;
    const int tid = threadIdx.x;
    const float4* __restrict__ grow =
        reinterpret_cast<const float4*>(g + (size_t)row * GN);
    const float4* __restrict__ w4 = reinterpret_cast<const float4*>(d_w2);

    // Front-batched loads for MLP
    float4 gv0 = grow[tid];
    float4 gv1 = grow[tid + 256];
    float4 gv2 = grow[tid + 512];
    float4 gv3 = grow[tid + 768];
    float4 wv0 = w4[tid];
    float4 wv1 = w4[tid + 256];
    float4 wv2 = w4[tid + 512];
    float4 wv3 = w4[tid + 768];

    float a0 = gv0.x * wv0.x + gv0.y * wv0.y + gv0.z * wv0.z + gv0.w * wv0.w;
    float a1 = gv1.x * wv1.x + gv1.y * wv1.y + gv1.z * wv1.z + gv1.w * wv1.w;
    float a2 = gv2.x * wv2.x + gv2.y * wv2.y + gv2.z * wv2.z + gv2.w * wv2.w;
    float a3 = gv3.x * wv3.x + gv3.y * wv3.y + gv3.z * wv3.z + gv3.w * wv3.w;
    float acc = (a0 + a1) + (a2 + a3);

    // Warp reduce
    #pragma unroll
    for (int o = 16; o > 0; o >>= 1)
        acc += __shfl_xor_sync(0xffffffffu, acc, o);

    __shared__ float red[8];
    __shared__ float vsh;
    if ((tid & 31) == 0) red[tid >> 5] = acc;
    __syncthreads();
    if (tid == 0) {
        float s = 0.f;
        #pragma unroll
        for (int i = 0; i < 8; i++) s += red[i];
        d_v[row] = s;
        vsh = s;
    }
    __syncthreads();

    // Fused F epilogue: F[row, t] = v * alpha[t]
    if (tid < TT)
        Fout[(size_t)row * TT + tid] = vsh * alphas[tid];
}

// ---------------------------------------------------------------------------
// Kernel 3: per-batch b:
//   ap[p]  = alpha[x_i[b,p]]
//   y[j]   = sum_p x[b,j,p] * ap[p]
//   Z[b,i] = sum_j v[i*64+j] * y[j]
// v staged into smem with stride-65 padding -> conflict-free GEMV.
// ---------------------------------------------------------------------------
__global__ void __launch_bounds__(256) k_z(const float* __restrict__ x,
                                           const int* __restrict__ xi,
                                           const float* __restrict__ alphas,
                                           float* __restrict__ Zout) {
    const int b = blockIdx.x;
    const int tid = threadIdx.x;
    __shared__ float ap[PP];
    __shared__ float y[NN];
    __shared__ float sv[NN * 65];

    // Stage v (16 KB, L2-hot after k_matvec) into padded smem
    for (int i = tid; i < GN; i += 256)
        sv[(i >> 6) * 65 + (i & 63)] = d_v[i];

    if (tid < PP)
        ap[tid] = alphas[xi[b * PP + tid]];
    __syncthreads();

    const int wid = tid >> 5, lane = tid & 31;
    // 8 warps, each handles rows j = wid, wid+8, ... (8 rows/warp)
    for (int j = wid; j < NN; j += 8) {
        const float* __restrict__ xr = x + ((size_t)b * NN + j) * PP;
        float s = xr[lane]      * ap[lane]
                + xr[lane + 32] * ap[lane + 32]
                + xr[lane + 64] * ap[lane + 64]
                + xr[lane + 96] * ap[lane + 96];
        #pragma unroll
        for (int o = 16; o > 0; o >>= 1)
            s += __shfl_xor_sync(0xffffffffu, s, o);
        if (lane == 0) y[j] = s;
    }
    __syncthreads();

    if (tid < NN) {
        float s = 0.f;
        #pragma unroll
        for (int j = 0; j < NN; j++)
            s += sv[tid * 65 + j] * y[j];
        Zout[b * NN + tid] = s;
    }
}

// ---------------------------------------------------------------------------
extern "C" void kernel_launch(void* const* d_in, const int* in_sizes, int n_in,
                              void* d_out, int out_size) {
    const float* x      = (const float*)d_in[0];   // [B, N, P]
    const int*   xi     = (const int*)  d_in[1];   // [B, P]
    const float* g      = (const float*)d_in[2];   // [N*N, N*N]
    const float* w      = (const float*)d_in[3];   // [N*N, 1]
    const float* alphas = (const float*)d_in[4];   // [1, T]

    float* out = (float*)d_out;
    float* Z = out;               // [B, N]      = 8192
    float* F = out + BB * NN;     // [N*N, T]    = 688128

    k_w2<<<(GN + 255) / 256, 256>>>(w);
    k_matvec<<<GN, 256>>>(g, alphas, F);
    k_z<<<BB, 256>>>(x, xi, alphas, Z);
}